// round 10
// baseline (speedup 1.0000x reference)
#include <cuda_runtime.h>
#include <stdint.h>

#define B_      8
#define IN_CH   64
#define OUT_CH  64
#define GROUPS  8
#define FPG     8
#define OPG     8
#define H_      256
#define W_      256

#define TY      16            // block stripe height
#define SROW    76            // smem row stride (floats) per warp subtile

// Warp subtile: 8 rows x 64 cols, halo 10 rows x 72 cols (18 aligned quads/row).
// Block = (b, g, 16-row stripe) = 8 warps in a 2(y) x 4(x) warp grid.
__global__ __launch_bounds__(256, 7)
void dynconv_fused(const float* __restrict__ x,
                   const float* __restrict__ rep,
                   const float* __restrict__ Wm,
                   float* __restrict__ out) {
    __shared__ float S[8][10][SROW];   // 8 warps x 10 x 76 x 4B = 24320 B
    __shared__ float kw[OPG][9];

    const int bg   = blockIdx.y;       // 0..63
    const int b    = bg >> 3;
    const int g    = bg & 7;
    const int ty0  = blockIdx.x * TY;
    const int tid  = threadIdx.x;
    const int w    = tid >> 5;
    const int lane = tid & 31;

    // ---- dynamic weights for this (b,g): threads 128..199, BEFORE any heavy mem ----
    if (tid >= 128 && tid < 128 + OPG * 9) {
        const int j   = tid - 128;     // 0..71
        const int ocl = j / 9;
        const int tap = j - ocl * 9;
        const float4* r  = (const float4*)(rep + b * 32);
        const float4* wv = (const float4*)(Wm + ((size_t)((g * OPG + ocl) * 9 + tap)) * 32);
        float s = 0.f;
#pragma unroll
        for (int i = 0; i < 8; i++) {
            float4 rv = r[i], ww = wv[i];
            s = fmaf(rv.x, ww.x, s);
            s = fmaf(rv.y, ww.y, s);
            s = fmaf(rv.z, ww.z, s);
            s = fmaf(rv.w, ww.w, s);
        }
        kw[ocl][tap] = (s > 0.f) ? s : 0.1f * s;
    }
    __syncthreads();   // only kw in flight; cheap. No barrier after this point.

    const size_t plane  = (size_t)H_ * W_;
    const size_t plane4 = plane / 4;
    const float* xg = x + ((size_t)b * IN_CH + (size_t)g * FPG) * plane;

    // ---- per-warp halo load: 10 rows x 18 quads, 8-channel sum ----
    const int wy     = w >> 2;          // 0..1
    const int wx     = w & 3;           // 0..3
    const int cw0    = wx * 64;         // subtile first col
    const int qstart = wx * 16 - 1;     // plane quad of smem quad 0
    const int rbase  = ty0 + wy * 8 - 1;  // plane row of smem row 0
    float (*Sw)[SROW] = S[w];

    for (int i = lane; i < 180; i += 32) {
        const int h  = i / 18;
        const int qx = i - h * 18;
        const int pq = qstart + qx;
        if (pq >= 0 && pq < 64) {
            int gy = rbase + h;
            gy = (gy < 0) ? -gy : ((gy >= H_) ? 2 * H_ - 2 - gy : gy);
            const float4* p = (const float4*)(xg + (size_t)gy * W_) + pq;
            float4 a = p[0];
#pragma unroll
            for (int c = 1; c < FPG; c++) {
                float4 v = p[c * plane4];
                a.x += v.x; a.y += v.y; a.z += v.z; a.w += v.w;
            }
            *(float4*)&Sw[h][qx * 4] = a;
        }
    }

    // x-edge reflect columns (only edge warps): col -1 -> 1, col 256 -> 254
    if (wx == 0 && lane < 10) {
        int gy = rbase + lane;
        gy = (gy < 0) ? -gy : ((gy >= H_) ? 2 * H_ - 2 - gy : gy);
        const float* p = xg + (size_t)gy * W_ + 1;
        float a = 0.f;
#pragma unroll
        for (int c = 0; c < FPG; c++) a += p[c * plane];
        Sw[lane][3] = a;
    }
    if (wx == 3 && lane < 10) {
        int gy = rbase + lane;
        gy = (gy < 0) ? -gy : ((gy >= H_) ? 2 * H_ - 2 - gy : gy);
        const float* p = xg + (size_t)gy * W_ + (W_ - 2);
        float a = 0.f;
#pragma unroll
        for (int c = 0; c < FPG; c++) a += p[c * plane];
        Sw[lane][68] = a;
    }

    __syncwarp();   // warp-private subtile: only this warp's STS must be visible

    // ---- compute: lane owns 4 cols x 4 rows x 8 oc ----
    const int q   = lane & 15;          // col quad within subtile
    const int rp  = lane >> 4;          // 0..1
    const int px0 = q * 4;
    const int r0  = rp * 4;             // first output row within subtile

    float* ob = out + ((size_t)b * OUT_CH + (size_t)g * OPG) * plane
                    + (size_t)(ty0 + wy * 8 + r0) * W_ + cw0 + px0;

    float w0[6], w1[6], w2[6];
#pragma unroll
    for (int k = 0; k < 6; k++) w0[k] = Sw[r0][3 + px0 + k];
#pragma unroll
    for (int k = 0; k < 6; k++) w1[k] = Sw[r0 + 1][3 + px0 + k];

#pragma unroll
    for (int rr = 0; rr < 4; rr++) {
#pragma unroll
        for (int k = 0; k < 6; k++) w2[k] = Sw[r0 + rr + 2][3 + px0 + k];

#pragma unroll
        for (int oc = 0; oc < OPG; oc++) {
            const float k0 = kw[oc][0], k1 = kw[oc][1], k2 = kw[oc][2];
            const float k3 = kw[oc][3], k4 = kw[oc][4], k5 = kw[oc][5];
            const float k6 = kw[oc][6], k7 = kw[oc][7], k8 = kw[oc][8];
            float4 v;
#pragma unroll
            for (int j = 0; j < 4; j++) {
                float a;
                a = w0[j] * k0;
                a = fmaf(w0[j + 1], k1, a);
                a = fmaf(w0[j + 2], k2, a);
                a = fmaf(w1[j],     k3, a);
                a = fmaf(w1[j + 1], k4, a);
                a = fmaf(w1[j + 2], k5, a);
                a = fmaf(w2[j],     k6, a);
                a = fmaf(w2[j + 1], k7, a);
                a = fmaf(w2[j + 2], k8, a);
                ((float*)&v)[j] = a;
            }
            __stcs((float4*)(ob + (size_t)oc * plane + (size_t)rr * W_), v);
        }

#pragma unroll
        for (int k = 0; k < 6; k++) { w0[k] = w1[k]; w1[k] = w2[k]; }
    }
}

extern "C" void kernel_launch(void* const* d_in, const int* in_sizes, int n_in,
                              void* d_out, int out_size) {
    const float* x   = (const float*)d_in[0];
    const float* rep = (const float*)d_in[1];
    const float* Wm  = (const float*)d_in[2];
    float* out = (float*)d_out;

    dim3 grid(H_ / TY, B_ * GROUPS);   // 16 x 64 = 1024 blocks, one wave
    dynconv_fused<<<grid, 256>>>(x, rep, Wm, out);
}

// round 11
// speedup vs baseline: 1.4749x; 1.4749x over previous
#include <cuda_runtime.h>
#include <stdint.h>

#define B_      8
#define IN_CH   64
#define OUT_CH  64
#define GROUPS  8
#define FPG     8
#define OPG     8
#define H_      256
#define W_      256

#define TY      16           // rows per tile
#define HY      (TY + 2)     // halo rows
#define SW      264          // smem row: 4 pad | 256 | 4 pad (16B-aligned)

// ---- tile loader: 8-channel sum with reflect halo, unpredicated float4 ----
__device__ __forceinline__ void load_tile(const float* __restrict__ xg,
                                          int ty0, float (*S)[SW],
                                          int tid, size_t plane) {
    const size_t plane4 = plane / 4;
    // interior: 18 rows x 64 aligned quads
    for (int q = tid; q < HY * 64; q += 256) {
        const int hy = q >> 6;
        const int qx = q & 63;
        int gy = ty0 + hy - 1;
        gy = (gy < 0) ? -gy : ((gy >= H_) ? 2 * H_ - 2 - gy : gy);
        const float4* p = (const float4*)(xg + (size_t)gy * W_) + qx;
        float4 a = p[0];
#pragma unroll
        for (int c = 1; c < FPG; c++) {
            float4 v = p[c * plane4];
            a.x += v.x; a.y += v.y; a.z += v.z; a.w += v.w;
        }
        *(float4*)&S[hy][4 + qx * 4] = a;
    }
    // x-edge reflect: gx=-1 -> 1, gx=256 -> 254
    if (tid >= 200 && tid < 200 + 2 * HY) {
        const int e    = tid - 200;
        const int hy   = e >> 1;
        const int side = e & 1;
        int gy = ty0 + hy - 1;
        gy = (gy < 0) ? -gy : ((gy >= H_) ? 2 * H_ - 2 - gy : gy);
        const float* p = xg + (size_t)gy * W_ + (side ? (W_ - 2) : 1);
        float a = 0.f;
#pragma unroll
        for (int c = 0; c < FPG; c++) a += p[c * plane];
        S[hy][side ? (4 + W_) : 3] = a;
    }
}

// ---- tile compute: thread owns 4 cols x 4 rows x 8 oc, float4 stores ----
__device__ __forceinline__ void compute_tile(const float (*S)[SW],
                                             const float (*kw)[9],
                                             float* __restrict__ outg,
                                             int ty0, int tid, size_t plane) {
    const int c   = tid & 63;
    const int r4  = tid >> 6;
    const int px0 = c * 4;
    const int y0  = r4 * 4;

    float* ob = outg + (size_t)(ty0 + y0) * W_ + px0;

    float w0[6], w1[6], w2[6];
#pragma unroll
    for (int k = 0; k < 6; k++) w0[k] = S[y0][3 + px0 + k];
#pragma unroll
    for (int k = 0; k < 6; k++) w1[k] = S[y0 + 1][3 + px0 + k];

#pragma unroll
    for (int rr = 0; rr < 4; rr++) {
#pragma unroll
        for (int k = 0; k < 6; k++) w2[k] = S[y0 + rr + 2][3 + px0 + k];

#pragma unroll
        for (int oc = 0; oc < OPG; oc++) {
            const float k0 = kw[oc][0], k1 = kw[oc][1], k2 = kw[oc][2];
            const float k3 = kw[oc][3], k4 = kw[oc][4], k5 = kw[oc][5];
            const float k6 = kw[oc][6], k7 = kw[oc][7], k8 = kw[oc][8];
            float4 v;
#pragma unroll
            for (int j = 0; j < 4; j++) {
                float a;
                a = w0[j] * k0;
                a = fmaf(w0[j + 1], k1, a);
                a = fmaf(w0[j + 2], k2, a);
                a = fmaf(w1[j],     k3, a);
                a = fmaf(w1[j + 1], k4, a);
                a = fmaf(w1[j + 2], k5, a);
                a = fmaf(w2[j],     k6, a);
                a = fmaf(w2[j + 1], k7, a);
                a = fmaf(w2[j + 2], k8, a);
                ((float*)&v)[j] = a;
            }
            *(float4*)(ob + (size_t)oc * plane + (size_t)rr * W_) = v;
        }

#pragma unroll
        for (int k = 0; k < 6; k++) { w0[k] = w1[k]; w1[k] = w2[k]; }
    }
}

// Block = (b, g, 32-row stripe) processed as two pipelined 16-row tiles:
//   load T0 | kw  -> bar -> load T1 (LDGs in flight) ; compute T0 -> bar -> compute T1
__global__ __launch_bounds__(256, 5)
void dynconv_pipe(const float* __restrict__ x,
                  const float* __restrict__ rep,
                  const float* __restrict__ Wm,
                  float* __restrict__ out) {
    __shared__ float S[2][HY][SW];     // 2 x 18 x 264 x 4B = 38016 B
    __shared__ float kw[OPG][9];

    const int bg  = blockIdx.y;        // 0..63
    const int b   = bg >> 3;
    const int g   = bg & 7;
    const int ty0 = blockIdx.x * (2 * TY);
    const int tid = threadIdx.x;

    const size_t plane = (size_t)H_ * W_;
    const float* xg = x + ((size_t)b * IN_CH + (size_t)g * FPG) * plane;
    float* outg = out + ((size_t)b * OUT_CH + (size_t)g * OPG) * plane;

    // dynamic weights (runs concurrently with tile-0 loads)
    if (tid >= 128 && tid < 128 + OPG * 9) {
        const int j   = tid - 128;
        const int ocl = j / 9;
        const int tap = j - ocl * 9;
        const float4* r  = (const float4*)(rep + b * 32);
        const float4* wv = (const float4*)(Wm + ((size_t)((g * OPG + ocl) * 9 + tap)) * 32);
        float s = 0.f;
#pragma unroll
        for (int i = 0; i < 8; i++) {
            float4 rv = r[i], ww = wv[i];
            s = fmaf(rv.x, ww.x, s);
            s = fmaf(rv.y, ww.y, s);
            s = fmaf(rv.z, ww.z, s);
            s = fmaf(rv.w, ww.w, s);
        }
        kw[ocl][tap] = (s > 0.f) ? s : 0.1f * s;
    }

    load_tile(xg, ty0, S[0], tid, plane);
    __syncthreads();                       // S[0] + kw ready

    load_tile(xg, ty0 + TY, S[1], tid, plane);   // loads overlap T0 compute
    compute_tile(S[0], kw, outg, ty0, tid, plane);
    __syncthreads();                       // S[1] ready

    compute_tile(S[1], kw, outg, ty0 + TY, tid, plane);
}

extern "C" void kernel_launch(void* const* d_in, const int* in_sizes, int n_in,
                              void* d_out, int out_size) {
    const float* x   = (const float*)d_in[0];
    const float* rep = (const float*)d_in[1];
    const float* Wm  = (const float*)d_in[2];
    float* out = (float*)d_out;

    dim3 grid(H_ / (2 * TY), B_ * GROUPS);   // 8 x 64 = 512 blocks
    dynconv_pipe<<<grid, 256>>>(x, rep, Wm, out);
}